// round 4
// baseline (speedup 1.0000x reference)
#include <cuda_runtime.h>
#include <cstdint>

// Fixed geometry: x_list (P=16384, N=1024, 2) float32, scale scalar.
// segn = N/4 = 256 segments per row; segment i uses points 3i..3i+3.
#define N_POINTS   1024
#define SEGN       256
#define NBLOCKS    608          // 152 SMs * 4 resident blocks -> exactly 1 wave
#define MAX_BLOCKS 1024

__device__ float        g_partials[MAX_BLOCKS];
__device__ unsigned int g_counter = 0;

// Compute the crossing term for segment t of one row, given its 4 points.
__device__ __forceinline__ float seg_term(float2 p0, float2 p1, float2 p2, float2 p3)
{
    const float v1x = p1.x - p0.x, v1y = p1.y - p0.y;
    const float v2x = p2.x - p1.x, v2y = p2.y - p1.y;
    const float v3x = p3.x - p2.x, v3y = p3.y - p2.y;

    // direct = (s12 >= 0) depends only on sign of cross(v1,v2):
    // the positive norm product cannot flip the sign.
    const float c12 = v1x * v2y - v1y * v2x;
    const float c13 = v1x * v3y - v1y * v3x;

    const float n2   = (v1x * v1x + v1y * v1y) * (v3x * v3x + v3y * v3y);
    const float sina = c13 * rsqrtf(n2);

    return (c12 >= 0.0f) ? fmaxf(-sina, 0.0f) : fmaxf(sina, 0.0f);
}

__global__ void __launch_bounds__(SEGN, 4) xing_kernel(
    const float* __restrict__ x,
    const uint32_t* __restrict__ scale_raw,
    float* __restrict__ out, int P, int nblocks)
{
    const int t = threadIdx.x;                 // segment index 0..255

    // Balanced contiguous row range for this block (26 or 27 rows).
    const int row_begin = (int)(((long long)blockIdx.x       * P) / nblocks);
    const int row_end   = (int)(((long long)(blockIdx.x + 1) * P) / nblocks);

    // Segment t starts at point 3t within each row.
    const float2* __restrict__ base =
        reinterpret_cast<const float2*>(x) + 3 * t;

    float acc = 0.0f;
    int row = row_begin;

    // 2-row batches: issue all 8 loads before any arithmetic (MLP = 8).
    for (; row + 2 <= row_end; row += 2) {
        const float2* pa = base + (size_t)row       * N_POINTS;
        const float2* pb = base + (size_t)(row + 1) * N_POINTS;
        float2 a0 = __ldg(pa + 0), a1 = __ldg(pa + 1), a2 = __ldg(pa + 2), a3 = __ldg(pa + 3);
        float2 b0 = __ldg(pb + 0), b1 = __ldg(pb + 1), b2 = __ldg(pb + 2), b3 = __ldg(pb + 3);
        acc += seg_term(a0, a1, a2, a3);
        acc += seg_term(b0, b1, b2, b3);
    }
    if (row < row_end) {
        const float2* pa = base + (size_t)row * N_POINTS;
        float2 a0 = __ldg(pa + 0), a1 = __ldg(pa + 1), a2 = __ldg(pa + 2), a3 = __ldg(pa + 3);
        acc += seg_term(a0, a1, a2, a3);
    }

    // ---- block reduce ----
    #pragma unroll
    for (int o = 16; o > 0; o >>= 1)
        acc += __shfl_down_sync(0xFFFFFFFFu, acc, o);

    __shared__ float s[SEGN / 32];
    __shared__ bool  isLast;
    if ((t & 31) == 0) s[t >> 5] = acc;
    __syncthreads();

    if (t == 0) {
        float bs = 0.0f;
        #pragma unroll
        for (int i = 0; i < SEGN / 32; i++) bs += s[i];
        g_partials[blockIdx.x] = bs;
        __threadfence();
        unsigned int done = atomicAdd(&g_counter, 1u);
        isLast = (done == (unsigned int)(nblocks - 1));
    }
    __syncthreads();

    // ---- last block folds the nblocks partials ----
    if (isLast) {
        float v = 0.0f;
        for (int i = t; i < nblocks; i += SEGN)
            v += __ldcg(&g_partials[i]);

        #pragma unroll
        for (int o = 16; o > 0; o >>= 1)
            v += __shfl_down_sync(0xFFFFFFFFu, v, o);
        if ((t & 31) == 0) s[t >> 5] = v;
        __syncthreads();

        if (t == 0) {
            float total = 0.0f;
            #pragma unroll
            for (int i = 0; i < SEGN / 32; i++) total += s[i];

            // Decode scale: float32 bit pattern vs integer bit pattern.
            uint32_t u = scale_raw[0];
            float    f = __uint_as_float(u);
            float    scale;
            if (fabsf(f) >= 1e-30f && fabsf(f) < 1e30f) scale = f;
            else                                        scale = (float)(int)u;

            out[0] = total * scale / ((float)SEGN * (float)P);
            // Reset counter for the next (graph-replayed) launch.
            atomicExch(&g_counter, 0u);
        }
    }
}

extern "C" void kernel_launch(void* const* d_in, const int* in_sizes, int n_in,
                              void* d_out, int out_size)
{
    const float*    x     = (const float*)d_in[0];
    const uint32_t* scale = (const uint32_t*)d_in[1];
    float*          out   = (float*)d_out;

    int P = in_sizes[0] / (N_POINTS * 2);     // 16384

    xing_kernel<<<NBLOCKS, SEGN>>>(x, scale, out, P, NBLOCKS);
}

// round 5
// speedup vs baseline: 1.2457x; 1.2457x over previous
#include <cuda_runtime.h>
#include <cstdint>

// Fixed geometry: x_list (P=16384, N=1024, 2) float32, scale scalar.
// segn = N/4 = 256 segments per row; segment i uses points 3i..3i+3.
#define N_POINTS        1024
#define SEGN            256
#define ROWS_PER_BLOCK  8
#define MAX_BLOCKS      4096

__device__ float        g_partials[MAX_BLOCKS];
__device__ unsigned int g_counter = 0;

__device__ __forceinline__ float2 ldcs2(const float2* p)
{
    // Streaming (evict-first) 64-bit load: data is single-use.
    float2 r;
    asm volatile("ld.global.cs.v2.f32 {%0, %1}, [%2];"
                 : "=f"(r.x), "=f"(r.y) : "l"(p));
    return r;
}

// Crossing term for one segment given its 4 points.
__device__ __forceinline__ float seg_term(float2 p0, float2 p1, float2 p2, float2 p3)
{
    const float v1x = p1.x - p0.x, v1y = p1.y - p0.y;
    const float v2x = p2.x - p1.x, v2y = p2.y - p1.y;
    const float v3x = p3.x - p2.x, v3y = p3.y - p2.y;

    // direct = (s12 >= 0) depends only on sign of cross(v1,v2):
    // the positive norm product cannot flip the sign.
    const float c12 = v1x * v2y - v1y * v2x;
    const float c13 = v1x * v3y - v1y * v3x;

    const float n2   = (v1x * v1x + v1y * v1y) * (v3x * v3x + v3y * v3y);
    const float sina = c13 * rsqrtf(n2);

    return (c12 >= 0.0f) ? fmaxf(-sina, 0.0f) : fmaxf(sina, 0.0f);
}

__global__ void __launch_bounds__(SEGN, 8) xing_kernel(
    const float* __restrict__ x,
    const uint32_t* __restrict__ scale_raw,
    float* __restrict__ out, int P, int nblocks)
{
    const int t = threadIdx.x;                 // segment index 0..255

    // Segment t starts at point 3t within each row.
    const float2* __restrict__ base =
        reinterpret_cast<const float2*>(x)
        + (size_t)blockIdx.x * ROWS_PER_BLOCK * N_POINTS + 3 * t;

    float acc = 0.0f;

    // 4 static iterations of 2-row batches: 8 independent LDG.64 in flight
    // before any arithmetic consumes them (MLP = 8 per thread).
    #pragma unroll
    for (int r = 0; r < ROWS_PER_BLOCK; r += 2) {
        const float2* pa = base + (size_t)r       * N_POINTS;
        const float2* pb = base + (size_t)(r + 1) * N_POINTS;
        float2 a0 = ldcs2(pa + 0), a1 = ldcs2(pa + 1), a2 = ldcs2(pa + 2), a3 = ldcs2(pa + 3);
        float2 b0 = ldcs2(pb + 0), b1 = ldcs2(pb + 1), b2 = ldcs2(pb + 2), b3 = ldcs2(pb + 3);
        acc += seg_term(a0, a1, a2, a3);
        acc += seg_term(b0, b1, b2, b3);
    }

    // ---- block reduce ----
    #pragma unroll
    for (int o = 16; o > 0; o >>= 1)
        acc += __shfl_down_sync(0xFFFFFFFFu, acc, o);

    __shared__ float s[SEGN / 32];
    __shared__ bool  isLast;
    if ((t & 31) == 0) s[t >> 5] = acc;
    __syncthreads();

    if (t == 0) {
        float bs = 0.0f;
        #pragma unroll
        for (int i = 0; i < SEGN / 32; i++) bs += s[i];
        g_partials[blockIdx.x] = bs;
        __threadfence();
        unsigned int done = atomicAdd(&g_counter, 1u);
        isLast = (done == (unsigned int)(nblocks - 1));
    }
    __syncthreads();

    // ---- last block folds the nblocks partials ----
    if (isLast) {
        float v = 0.0f;
        for (int i = t; i < nblocks; i += SEGN)
            v += __ldcg(&g_partials[i]);

        #pragma unroll
        for (int o = 16; o > 0; o >>= 1)
            v += __shfl_down_sync(0xFFFFFFFFu, v, o);
        if ((t & 31) == 0) s[t >> 5] = v;
        __syncthreads();

        if (t == 0) {
            float total = 0.0f;
            #pragma unroll
            for (int i = 0; i < SEGN / 32; i++) total += s[i];

            // Decode scale: float32 bit pattern vs integer bit pattern.
            uint32_t u = scale_raw[0];
            float    f = __uint_as_float(u);
            float    scale;
            if (fabsf(f) >= 1e-30f && fabsf(f) < 1e30f) scale = f;
            else                                        scale = (float)(int)u;

            out[0] = total * scale / ((float)SEGN * (float)P);
            // Reset counter for the next (graph-replayed) launch.
            atomicExch(&g_counter, 0u);
        }
    }
}

extern "C" void kernel_launch(void* const* d_in, const int* in_sizes, int n_in,
                              void* d_out, int out_size)
{
    const float*    x     = (const float*)d_in[0];
    const uint32_t* scale = (const uint32_t*)d_in[1];
    float*          out   = (float*)d_out;

    int P       = in_sizes[0] / (N_POINTS * 2);     // 16384
    int nblocks = P / ROWS_PER_BLOCK;               // 2048

    xing_kernel<<<nblocks, SEGN>>>(x, scale, out, P, nblocks);
}